// round 1
// baseline (speedup 1.0000x reference)
#include <cuda_runtime.h>
#include <math.h>

// Problem dimensions (fixed for this dataset entry)
#define BDIM 512
#define TDIM 512
#define IN0  64
#define HDIM 128
#define G3   384   // 3*H  (gate order r, z, n)

// ---------------------------------------------------------------------------
// Scratch (allocation-free: __device__ globals per harness rules)
// ---------------------------------------------------------------------------
__device__ float g_gi   [(size_t)BDIM * TDIM * G3];   // 402 MB: gate preacts, reused per layer
__device__ float g_h1   [(size_t)BDIM * TDIM * HDIM]; // 134 MB: layer-0 hidden sequence
__device__ float g_hlast[(size_t)BDIM * HDIM];        // final hidden of layer 1

// ---------------------------------------------------------------------------
// gi GEMM: out[M, 384] = X[M, K] @ W[384, K]^T + bias   (M = B*T)
// CTA: 64 rows, 256 threads. W staged in smem in 4 chunks of 96 gates.
// Thread computes 4 rows x 6 gates (24 accumulators).
// ---------------------------------------------------------------------------
template <int K>
__global__ __launch_bounds__(256)
void gi_gemm(const float* __restrict__ X,
             const float* __restrict__ W,
             const float* __restrict__ bias)
{
    constexpr int TM = 64;
    constexpr int NC = 96;        // gates per chunk
    constexpr int XP = TM + 1;    // 65, odd pitch -> conflict-free transposed store
    constexpr int WP = K + 1;     // odd pitch -> conflict-free strided gate reads

    extern __shared__ float sm[];
    float* xs = sm;               // [K][XP]   xs[k*XP + r]
    float* ws = sm + K * XP;      // [NC][WP]  ws[g*WP + k]

    const int tid = threadIdx.x;
    const int rowbase = blockIdx.x * TM;

    // Stage X tile transposed: coalesced global read, stride-65 smem write.
    for (int idx = tid; idx < TM * K; idx += 256) {
        int r = idx / K, k = idx - r * K;
        xs[k * XP + r] = X[(size_t)(rowbase + r) * K + k];
    }

    const int rg = tid >> 4;      // 0..15 : row group (4 rows)
    const int gg = tid & 15;      // 0..15 : gate group (6 gates)

    float* out = g_gi;

    for (int c = 0; c < 4; ++c) {
        __syncthreads();          // xs ready (c==0) / previous compute done
        for (int idx = tid; idx < NC * K; idx += 256) {
            int g = idx / K, k = idx - g * K;
            ws[g * WP + k] = W[(size_t)(c * NC + g) * K + k];
        }
        __syncthreads();

        float acc[4][6];
        #pragma unroll
        for (int i = 0; i < 4; ++i)
            #pragma unroll
            for (int j = 0; j < 6; ++j) acc[i][j] = 0.f;

        const float* wp0 = &ws[(gg * 6) * WP];
        const float* xp0 = &xs[rg * 4];

        #pragma unroll 4
        for (int k = 0; k < K; ++k) {
            float xv0 = xp0[k * XP + 0];
            float xv1 = xp0[k * XP + 1];
            float xv2 = xp0[k * XP + 2];
            float xv3 = xp0[k * XP + 3];
            #pragma unroll
            for (int j = 0; j < 6; ++j) {
                float w = wp0[j * WP + k];
                acc[0][j] += xv0 * w;
                acc[1][j] += xv1 * w;
                acc[2][j] += xv2 * w;
                acc[3][j] += xv3 * w;
            }
        }

        #pragma unroll
        for (int j = 0; j < 6; ++j) {
            int g = c * NC + gg * 6 + j;
            float bv = bias[g];
            #pragma unroll
            for (int i = 0; i < 4; ++i) {
                int r = rowbase + rg * 4 + i;
                out[(size_t)r * G3 + g] = acc[i][j] + bv;
            }
        }
    }
}

// ---------------------------------------------------------------------------
// Persistent GRU recurrence. One CTA owns 4 batch rows for all T steps.
// W_hh lives (transposed) in smem for the whole kernel; h state in smem.
// 512 threads = (j in 0..127) x (q in 0..3, quarter of the k-reduction).
// Step: partial matvec (12 acc: 3 gates x 4 batches over 32 k)
//       -> smem reduce -> gates (thread (j,q) finishes batch q) -> h update.
// ---------------------------------------------------------------------------
template <int WRITE_SEQ>
__global__ __launch_bounds__(512)
void gru_recurrent(const float* __restrict__ Whh,
                   const float* __restrict__ bhh)
{
    constexpr int BB = 4;
    constexpr int RP = 13;        // reduction pitch (odd -> conflict-free)

    extern __shared__ float sm[];
    float* Wt  = sm;                         // [128][384]  Wt[k*384 + g]
    float* hs  = Wt + HDIM * G3;             // [128][4]    hs[k*4 + b]
    float* red = hs + HDIM * BB;             // [4][128][RP]
    float* bh  = red + 4 * HDIM * RP;        // [384]

    const int tid = threadIdx.x;
    const int j   = tid & 127;
    const int q   = tid >> 7;                // 0..3
    const int b0  = blockIdx.x * BB;

    // Stage W_hh transposed (coalesced read; one-time strided write).
    for (int idx = tid; idx < G3 * HDIM; idx += 512) {
        int g = idx >> 7;
        int k = idx & 127;
        Wt[k * G3 + g] = Whh[idx];
    }
    for (int idx = tid; idx < G3; idx += 512) bh[idx] = bhh[idx];
    for (int idx = tid; idx < HDIM * BB; idx += 512) hs[idx] = 0.f;
    __syncthreads();

    const int k0 = q * 32;
    float* myred = &red[(q * HDIM + j) * RP];
    const float* gi = g_gi;

    for (int t = 0; t < TDIM; ++t) {
        // Prefetch this step's input-side preactivations (batch q) early;
        // the ~3000-cycle matvec below hides the DRAM latency.
        const float* gip = gi + ((size_t)(b0 + q) * TDIM + t) * G3;
        float ir  = gip[j];
        float iz  = gip[HDIM + j];
        float in_ = gip[2 * HDIM + j];

        float acc[12];
        #pragma unroll
        for (int i = 0; i < 12; ++i) acc[i] = 0.f;

        const float2* h2 = (const float2*)hs;
        #pragma unroll 8
        for (int kk = 0; kk < 32; ++kk) {
            int k = k0 + kk;
            float wr = Wt[k * G3 + j];
            float wz = Wt[k * G3 + HDIM + j];
            float wn = Wt[k * G3 + 2 * HDIM + j];
            float2 h01 = h2[k * 2];
            float2 h23 = h2[k * 2 + 1];
            acc[0] += wr * h01.x;  acc[1]  += wr * h01.y;
            acc[2] += wr * h23.x;  acc[3]  += wr * h23.y;
            acc[4] += wz * h01.x;  acc[5]  += wz * h01.y;
            acc[6] += wz * h23.x;  acc[7]  += wz * h23.y;
            acc[8] += wn * h01.x;  acc[9]  += wn * h01.y;
            acc[10]+= wn * h23.x;  acc[11] += wn * h23.y;
        }
        #pragma unroll
        for (int i = 0; i < 12; ++i) myred[i] = acc[i];
        __syncthreads();

        // Gate phase: thread (j, q) finishes batch b = q.
        const int b = q;
        float sr = 0.f, sz = 0.f, sn = 0.f;
        #pragma unroll
        for (int qq = 0; qq < 4; ++qq) {
            const float* rp = &red[(qq * HDIM + j) * RP];
            sr += rp[0 * 4 + b];
            sz += rp[1 * 4 + b];
            sn += rp[2 * 4 + b];
        }
        float ghr = sr + bh[j];
        float ghz = sz + bh[HDIM + j];
        float ghn = sn + bh[2 * HDIM + j];
        float r = __fdividef(1.f, 1.f + __expf(-(ir + ghr)));
        float z = __fdividef(1.f, 1.f + __expf(-(iz + ghz)));
        float n = tanhf(in_ + r * ghn);
        float hold = hs[j * 4 + b];
        float hnew = n + z * (hold - n);     // (1-z)*n + z*h

        hs[j * 4 + b] = hnew;
        if (WRITE_SEQ) {
            g_h1[((size_t)(b0 + b) * TDIM + t) * HDIM + j] = hnew;
        } else if (t == TDIM - 1) {
            g_hlast[(b0 + b) * HDIM + j] = hnew;
        }
        __syncthreads();
    }
}

// ---------------------------------------------------------------------------
// Final FC: out[b] = h_last[b] . W_fc + b_fc   (O = 1). One warp per batch.
// ---------------------------------------------------------------------------
__global__ void fc_kernel(const float* __restrict__ Wfc,
                          const float* __restrict__ bfc,
                          float* __restrict__ out)
{
    int w = (blockIdx.x * blockDim.x + threadIdx.x) >> 5;
    int lane = threadIdx.x & 31;
    if (w >= BDIM) return;
    const float* hp = g_hlast + (size_t)w * HDIM;
    float s = 0.f;
    #pragma unroll
    for (int k = lane; k < HDIM; k += 32) s += hp[k] * Wfc[k];
    #pragma unroll
    for (int o = 16; o; o >>= 1) s += __shfl_xor_sync(0xFFFFFFFFu, s, o);
    if (lane == 0) out[w] = s + bfc[0];
}

// ---------------------------------------------------------------------------
extern "C" void kernel_launch(void* const* d_in, const int* in_sizes, int n_in,
                              void* d_out, int out_size)
{
    const float* x     = (const float*)d_in[0];
    const float* W_ih0 = (const float*)d_in[1];
    const float* W_hh0 = (const float*)d_in[2];
    const float* b_ih0 = (const float*)d_in[3];
    const float* b_hh0 = (const float*)d_in[4];
    const float* W_ih1 = (const float*)d_in[5];
    const float* W_hh1 = (const float*)d_in[6];
    const float* b_ih1 = (const float*)d_in[7];
    const float* b_hh1 = (const float*)d_in[8];
    const float* W_fc  = (const float*)d_in[9];
    const float* b_fc  = (const float*)d_in[10];
    float* out = (float*)d_out;

    // smem sizes
    const int SMEM_G64  = (64 * 65 + 96 * 65) * 4;            // 41,600 B
    const int SMEM_G128 = (128 * 65 + 96 * 129) * 4;          // 82,816 B
    const int SMEM_REC  = (HDIM * G3 + HDIM * 4 + 4 * HDIM * 13 + G3) * 4; // 226,816 B

    cudaFuncSetAttribute(gi_gemm<64>,  cudaFuncAttributeMaxDynamicSharedMemorySize, SMEM_G64);
    cudaFuncSetAttribute(gi_gemm<128>, cudaFuncAttributeMaxDynamicSharedMemorySize, SMEM_G128);
    cudaFuncSetAttribute(gru_recurrent<1>, cudaFuncAttributeMaxDynamicSharedMemorySize, SMEM_REC);
    cudaFuncSetAttribute(gru_recurrent<0>, cudaFuncAttributeMaxDynamicSharedMemorySize, SMEM_REC);

    void* h1ptr = nullptr;
    cudaGetSymbolAddress(&h1ptr, g_h1);

    const int M = BDIM * TDIM;            // 262144 rows
    const int GEMM_GRID = M / 64;         // 4096

    // Layer 0: gi0 = x @ W_ih0^T + b_ih0
    gi_gemm<64><<<GEMM_GRID, 256, SMEM_G64>>>(x, W_ih0, b_ih0);
    // Layer 0 recurrence -> g_h1 (full sequence)
    gru_recurrent<1><<<BDIM / 4, 512, SMEM_REC>>>(W_hh0, b_hh0);
    // Layer 1: gi1 = h1 @ W_ih1^T + b_ih1
    gi_gemm<128><<<GEMM_GRID, 256, SMEM_G128>>>((const float*)h1ptr, W_ih1, b_ih1);
    // Layer 1 recurrence -> g_hlast (last step only)
    gru_recurrent<0><<<BDIM / 4, 512, SMEM_REC>>>(W_hh1, b_hh1);
    // Final FC
    fc_kernel<<<BDIM / 4, 128>>>(W_fc, b_fc, out);
}

// round 2
// speedup vs baseline: 1.2608x; 1.2608x over previous
#include <cuda_runtime.h>
#include <math.h>

#define BDIM 512
#define TDIM 512
#define IN0  64
#define HDIM 128
#define G3   384   // 3*H  (gate order r, z, n)

typedef unsigned long long u64;

// ---------------------------------------------------------------------------
// f32x2 packed helpers (sm_103a packed fp32 pipe; only reachable via PTX)
// ---------------------------------------------------------------------------
__device__ __forceinline__ u64 pack2u(unsigned int lo, unsigned int hi) {
    u64 r; asm("mov.b64 %0, {%1, %2};" : "=l"(r) : "r"(lo), "r"(hi)); return r;
}
__device__ __forceinline__ u64 splat2(unsigned int v) {
    u64 r; asm("mov.b64 %0, {%1, %1};" : "=l"(r) : "r"(v)); return r;
}
__device__ __forceinline__ void fma2(u64& d, u64 a, u64 b) {
    asm("fma.rn.f32x2 %0, %1, %2, %0;" : "+l"(d) : "l"(a), "l"(b));
}
__device__ __forceinline__ float2 unpack2(u64 v) {
    unsigned int lo, hi;
    asm("mov.b64 {%0, %1}, %2;" : "=r"(lo), "=r"(hi) : "l"(v));
    float2 f; f.x = __uint_as_float(lo); f.y = __uint_as_float(hi); return f;
}

// ---------------------------------------------------------------------------
// Scratch (allocation-free: __device__ globals)
// ---------------------------------------------------------------------------
__device__ float g_gi   [(size_t)BDIM * TDIM * G3];
__device__ float g_h1   [(size_t)BDIM * TDIM * HDIM];
__device__ float g_hlast[(size_t)BDIM * HDIM];

// ---------------------------------------------------------------------------
// gi GEMM: out[M, 384] = X[M, K] @ W[384, K]^T + bias   (M = B*T)
// CTA: 64 rows, 256 threads, W staged per 96-gate chunk in [k][gate] layout
// so adjacent gates load as LDS.64 and accumulate as f32x2 pairs.
// Thread: 4 rows x 3 gate-pairs = 12 f32x2 accumulators.
// ---------------------------------------------------------------------------
template <int K>
__global__ __launch_bounds__(256)
void gi_gemm(const float* __restrict__ X,
             const float* __restrict__ W,
             const float* __restrict__ bias)
{
    constexpr int TM  = 64;
    constexpr int NC  = 96;
    constexpr int XP  = 66;     // even pitch -> 8B-aligned row pairs, conflict-free
    constexpr int WP2 = 98;     // even pitch, [k][gate] layout

    extern __shared__ float sm[];
    float* xs = sm;             // [K][XP]   xs[k*XP + r]
    float* ws = sm + K * XP;    // [K][WP2]  ws[k*WP2 + g]

    const int tid = threadIdx.x;
    const int rowbase = blockIdx.x * TM;

    for (int idx = tid; idx < TM * K; idx += 256) {
        int r = idx / K, k = idx - r * K;
        xs[k * XP + r] = X[(size_t)(rowbase + r) * K + k];
    }

    const int rg = tid >> 4;    // 0..15 row group (4 rows)
    const int gg = tid & 15;    // 0..15 gate group (6 gates = 3 pairs)

    float* out = g_gi;

    for (int c = 0; c < 4; ++c) {
        __syncthreads();
        for (int idx = tid; idx < NC * K; idx += 256) {
            int g = idx / K, k = idx - g * K;
            ws[k * WP2 + g] = W[(size_t)(c * NC + g) * K + k];
        }
        __syncthreads();

        u64 acc[4][3];
        #pragma unroll
        for (int i = 0; i < 4; ++i)
            #pragma unroll
            for (int p = 0; p < 3; ++p) acc[i][p] = 0ull;

        const float* xp0 = &xs[rg * 4];
        const float* wp0 = &ws[gg * 6];

        #pragma unroll 4
        for (int k = 0; k < K; ++k) {
            u64 x0 = splat2(__float_as_uint(xp0[k * XP + 0]));
            u64 x1 = splat2(__float_as_uint(xp0[k * XP + 1]));
            u64 x2 = splat2(__float_as_uint(xp0[k * XP + 2]));
            u64 x3 = splat2(__float_as_uint(xp0[k * XP + 3]));
            const u64* wrow = (const u64*)&wp0[k * WP2];  // 8B aligned: WP2, gg*6 even
            u64 w01 = wrow[0], w23 = wrow[1], w45 = wrow[2];
            fma2(acc[0][0], x0, w01); fma2(acc[0][1], x0, w23); fma2(acc[0][2], x0, w45);
            fma2(acc[1][0], x1, w01); fma2(acc[1][1], x1, w23); fma2(acc[1][2], x1, w45);
            fma2(acc[2][0], x2, w01); fma2(acc[2][1], x2, w23); fma2(acc[2][2], x2, w45);
            fma2(acc[3][0], x3, w01); fma2(acc[3][1], x3, w23); fma2(acc[3][2], x3, w45);
        }

        const int g0 = c * NC + gg * 6;
        #pragma unroll
        for (int p = 0; p < 3; ++p) {
            float b0 = bias[g0 + 2 * p];
            float b1 = bias[g0 + 2 * p + 1];
            #pragma unroll
            for (int i = 0; i < 4; ++i) {
                float2 v = unpack2(acc[i][p]);
                size_t r = (size_t)(rowbase + rg * 4 + i);
                out[r * G3 + g0 + 2 * p]     = v.x + b0;
                out[r * G3 + g0 + 2 * p + 1] = v.y + b1;
            }
        }
    }
}

// ---------------------------------------------------------------------------
// Persistent GRU recurrence. One CTA = 4 batch rows for all T steps.
// Thread (j in 0..127, q in 0..3): j = hidden unit, q = k-quarter.
// r/z gate weights live in REGISTERS (64 regs, fixed per thread across t);
// n gate weights in smem. Batch pairs (0,1),(2,3) packed as f32x2.
// ---------------------------------------------------------------------------
template <int WRITE_SEQ>
__global__ __launch_bounds__(512, 1)
void gru_recurrent(const float* __restrict__ Whh,
                   const float* __restrict__ bhh)
{
    constexpr int RP = 13;

    extern __shared__ float sm[];
    float* Wn  = sm;                          // [128][128] Wn[k*128 + j]
    float* hs  = Wn + HDIM * HDIM;            // [128][4]
    float* red = hs + HDIM * 4;               // [4][128][RP]
    float* bh  = red + 4 * HDIM * RP;         // [384]

    const int tid = threadIdx.x;
    const int j   = tid & 127;
    const int q   = tid >> 7;
    const int b0  = blockIdx.x * 4;
    const int k0  = q * 32;

    // Stage n-gate weights transposed into smem (one-time).
    for (int idx = tid; idx < HDIM * HDIM; idx += 512) {
        int g = idx >> 7;          // row within n block
        int k = idx & 127;
        Wn[k * HDIM + g] = Whh[(size_t)(2 * HDIM + g) * HDIM + k];
    }
    for (int idx = tid; idx < G3; idx += 512) bh[idx] = bhh[idx];
    for (int idx = tid; idx < HDIM * 4; idx += 512) hs[idx] = 0.f;

    // r/z weights into registers: wrz[2*kk] = Wr[j][k0+kk], wrz[2*kk+1] = Wz[j][k0+kk]
    unsigned int wrz[64];
    {
        const float* wr_row = Whh + (size_t)j * HDIM + k0;
        const float* wz_row = Whh + (size_t)(HDIM + j) * HDIM + k0;
        #pragma unroll
        for (int kk = 0; kk < 32; ++kk) {
            wrz[2 * kk]     = __float_as_uint(__ldg(wr_row + kk));
            wrz[2 * kk + 1] = __float_as_uint(__ldg(wz_row + kk));
        }
    }
    __syncthreads();

    float* myred = &red[(q * HDIM + j) * RP];
    const float* gi = g_gi + (size_t)(b0 + q) * TDIM * G3;
    const u64* hs64 = (const u64*)hs;
    const float* wnp = &Wn[(size_t)k0 * HDIM + j];

    for (int t = 0; t < TDIM; ++t) {
        // Prefetch this step's input-side preactivations early (DRAM latency
        // hidden behind the matvec below).
        const float* gip = gi + (size_t)t * G3;
        float ir  = gip[j];
        float iz  = gip[HDIM + j];
        float in_ = gip[2 * HDIM + j];

        u64 a_r01 = 0, a_r23 = 0, a_z01 = 0, a_z23 = 0, a_n01 = 0, a_n23 = 0;

        #pragma unroll
        for (int kk = 0; kk < 32; ++kk) {
            u64 h01 = hs64[(k0 + kk) * 2];         // warp-broadcast LDS.64
            u64 h23 = hs64[(k0 + kk) * 2 + 1];
            u64 wr2 = splat2(wrz[2 * kk]);
            u64 wz2 = splat2(wrz[2 * kk + 1]);
            u64 wn2 = splat2(__float_as_uint(wnp[kk * HDIM]));
            fma2(a_r01, wr2, h01); fma2(a_r23, wr2, h23);
            fma2(a_z01, wz2, h01); fma2(a_z23, wz2, h23);
            fma2(a_n01, wn2, h01); fma2(a_n23, wn2, h23);
        }

        {
            float2 v;
            v = unpack2(a_r01); myred[0] = v.x; myred[1] = v.y;
            v = unpack2(a_r23); myred[2] = v.x; myred[3] = v.y;
            v = unpack2(a_z01); myred[4] = v.x; myred[5] = v.y;
            v = unpack2(a_z23); myred[6] = v.x; myred[7] = v.y;
            v = unpack2(a_n01); myred[8] = v.x; myred[9] = v.y;
            v = unpack2(a_n23); myred[10] = v.x; myred[11] = v.y;
        }
        __syncthreads();

        // Gate phase: thread (j, q) finishes batch b = q.
        const int b = q;
        float sr = 0.f, sz = 0.f, sn = 0.f;
        #pragma unroll
        for (int qq = 0; qq < 4; ++qq) {
            const float* rp = &red[(qq * HDIM + j) * RP];
            sr += rp[0 * 4 + b];
            sz += rp[1 * 4 + b];
            sn += rp[2 * 4 + b];
        }
        float ghr = sr + bh[j];
        float ghz = sz + bh[HDIM + j];
        float ghn = sn + bh[2 * HDIM + j];
        float r = __fdividef(1.f, 1.f + __expf(-(ir + ghr)));
        float z = __fdividef(1.f, 1.f + __expf(-(iz + ghz)));
        float n = tanhf(in_ + r * ghn);
        float hold = hs[j * 4 + b];
        float hnew = n + z * (hold - n);

        hs[j * 4 + b] = hnew;
        if (WRITE_SEQ) {
            g_h1[((size_t)(b0 + b) * TDIM + t) * HDIM + j] = hnew;
        } else if (t == TDIM - 1) {
            g_hlast[(size_t)(b0 + b) * HDIM + j] = hnew;
        }
        __syncthreads();
    }
}

// ---------------------------------------------------------------------------
// Final FC: out[b] = h_last[b] . W_fc + b_fc   (O = 1). One warp per batch.
// ---------------------------------------------------------------------------
__global__ void fc_kernel(const float* __restrict__ Wfc,
                          const float* __restrict__ bfc,
                          float* __restrict__ out)
{
    int w = (blockIdx.x * blockDim.x + threadIdx.x) >> 5;
    int lane = threadIdx.x & 31;
    if (w >= BDIM) return;
    const float* hp = g_hlast + (size_t)w * HDIM;
    float s = 0.f;
    #pragma unroll
    for (int k = lane; k < HDIM; k += 32) s += hp[k] * Wfc[k];
    #pragma unroll
    for (int o = 16; o; o >>= 1) s += __shfl_xor_sync(0xFFFFFFFFu, s, o);
    if (lane == 0) out[w] = s + bfc[0];
}

// ---------------------------------------------------------------------------
extern "C" void kernel_launch(void* const* d_in, const int* in_sizes, int n_in,
                              void* d_out, int out_size)
{
    const float* x     = (const float*)d_in[0];
    const float* W_ih0 = (const float*)d_in[1];
    const float* W_hh0 = (const float*)d_in[2];
    const float* b_ih0 = (const float*)d_in[3];
    const float* b_hh0 = (const float*)d_in[4];
    const float* W_ih1 = (const float*)d_in[5];
    const float* W_hh1 = (const float*)d_in[6];
    const float* b_ih1 = (const float*)d_in[7];
    const float* b_hh1 = (const float*)d_in[8];
    const float* W_fc  = (const float*)d_in[9];
    const float* b_fc  = (const float*)d_in[10];
    float* out = (float*)d_out;

    const int SMEM_G64  = (64  * 66 + 64  * 98) * 4;   // 41,984 B
    const int SMEM_G128 = (128 * 66 + 128 * 98) * 4;   // 83,968 B
    const int SMEM_REC  = (HDIM * HDIM + HDIM * 4 + 4 * HDIM * 13 + G3) * 4; // 95,744 B

    cudaFuncSetAttribute(gi_gemm<64>,  cudaFuncAttributeMaxDynamicSharedMemorySize, SMEM_G64);
    cudaFuncSetAttribute(gi_gemm<128>, cudaFuncAttributeMaxDynamicSharedMemorySize, SMEM_G128);
    cudaFuncSetAttribute(gru_recurrent<1>, cudaFuncAttributeMaxDynamicSharedMemorySize, SMEM_REC);
    cudaFuncSetAttribute(gru_recurrent<0>, cudaFuncAttributeMaxDynamicSharedMemorySize, SMEM_REC);

    void* h1ptr = nullptr;
    cudaGetSymbolAddress(&h1ptr, g_h1);

    const int M = BDIM * TDIM;
    const int GEMM_GRID = M / 64;

    gi_gemm<64><<<GEMM_GRID, 256, SMEM_G64>>>(x, W_ih0, b_ih0);
    gru_recurrent<1><<<BDIM / 4, 512, SMEM_REC>>>(W_hh0, b_hh0);
    gi_gemm<128><<<GEMM_GRID, 256, SMEM_G128>>>((const float*)h1ptr, W_ih1, b_ih1);
    gru_recurrent<0><<<BDIM / 4, 512, SMEM_REC>>>(W_hh1, b_hh1);
    fc_kernel<<<BDIM / 4, 128>>>(W_fc, b_fc, out);
}